// round 1
// baseline (speedup 1.0000x reference)
#include <cuda_runtime.h>
#include <math.h>
#include <float.h>

// Problem dims
#define T_SEQ 256
#define BATCH 512
#define IND   128
#define H1D   100
#define G1D   400     // 4*H1
#define H2D   128
#define G2D   512     // 4*H2
#define NC    19

// ---------------- scratch (device globals: no allocation allowed) ----------
__device__ float g_zx1[256u*512u*400u];   // [T][B][4*H1]  ~210MB
__device__ float g_h1 [256u*512u*100u];   // [T][B][H1]    ~52MB
__device__ float g_zx2[256u*512u*512u];   // [T][B][4*H2]  ~268MB
__device__ float g_h2 [512u*128u];        // [B][H2]

// ---------------- generic feedforward GEMM: C = A(MxK) * B(KxN) + bias -----
// mode==1: A row m=(t*B+b) gathered from x[b][t][:] (x layout [B][T][D])
// mode==0: A rows contiguous with stride K
#define BM 64
#define BN 64
#define KMAX 128
#define AP 68   // padded lda for transposed A tile (16B-aligned rows)

__global__ __launch_bounds__(256, 3)
void gemm_ff(const float* __restrict__ A, const float* __restrict__ Bw,
             const float* __restrict__ bias, float* __restrict__ C,
             int M, int N, int K, int mode)
{
    extern __shared__ float sm[];
    float* As = sm;                 // [KMAX][AP], stores A^T tile: As[k][mloc]
    float* Bs = sm + KMAX * AP;     // [KMAX][BN]

    const int tid = threadIdx.x;
    const int m0 = blockIdx.x * BM;
    const int n0 = blockIdx.y * BN;

    // load A tile (transposed)
    for (int idx = tid; idx < BM * K; idx += 256) {
        int mloc = idx / K;
        int k = idx - mloc * K;
        int m = m0 + mloc;
        size_t arow;
        if (mode) { int t = m >> 9; int b = m & 511; arow = ((size_t)(b * T_SEQ + t)) * IND; }
        else      { arow = (size_t)m * K; }
        As[k * AP + mloc] = A[arow + k];
    }
    // load B tile
    for (int idx = tid; idx < K * BN; idx += 256) {
        int k = idx >> 6;
        int n = idx & 63;
        int gn = n0 + n;
        Bs[k * BN + n] = (gn < N) ? Bw[(size_t)k * N + gn] : 0.f;
    }
    __syncthreads();

    const int tx = tid & 15, ty = tid >> 4;
    float acc[4][4];
#pragma unroll
    for (int i = 0; i < 4; i++)
#pragma unroll
        for (int j = 0; j < 4; j++) acc[i][j] = 0.f;

#pragma unroll 4
    for (int k = 0; k < K; ++k) {
        float4 av = *reinterpret_cast<const float4*>(&As[k * AP + ty * 4]);
        float4 bv = *reinterpret_cast<const float4*>(&Bs[k * BN + tx * 4]);
        float a[4] = {av.x, av.y, av.z, av.w};
        float b[4] = {bv.x, bv.y, bv.z, bv.w};
#pragma unroll
        for (int i = 0; i < 4; i++)
#pragma unroll
            for (int j = 0; j < 4; j++) acc[i][j] = fmaf(a[i], b[j], acc[i][j]);
    }

#pragma unroll
    for (int i = 0; i < 4; i++) {
        int m = m0 + ty * 4 + i;
        int n = n0 + tx * 4;
        float* cp = &C[(size_t)m * N + n];
        if (n + 3 < N) {
            float4 v;
            v.x = acc[i][0] + bias[n + 0];
            v.y = acc[i][1] + bias[n + 1];
            v.z = acc[i][2] + bias[n + 2];
            v.w = acc[i][3] + bias[n + 3];
            *reinterpret_cast<float4*>(cp) = v;
        } else {
#pragma unroll
            for (int j = 0; j < 4; j++)
                if (n + j < N) cp[j] = acc[i][j] + bias[n + j];
        }
    }
}

// ---------------- layer-1 scan: U1 (100x400) fully register-resident -------
// Block = 4 batch rows, 512 threads. Phase 1: thread tid<400 owns column tid
// of z (holds U1[:,tid] in 100 registers); h state in smem as [j][4] so one
// broadcast LDS.128 feeds 4 FFMAs. Phase 2: thread (r,j) owns cell state c.
__global__ __launch_bounds__(512, 1)
void lstm_scan1(const float* __restrict__ zx, const float* __restrict__ U,
                float* __restrict__ hout)
{
    __shared__ float4 h4[H1D];       // h[j] packed over 4 rows
    __shared__ float  zs[4 * G1D];   // activated gate values per step

    const int tid = threadIdx.x;
    const int b0 = blockIdx.x * 4;

    float Ureg[H1D];
    if (tid < G1D) {
#pragma unroll
        for (int j = 0; j < H1D; ++j) Ureg[j] = U[j * G1D + tid];
    }
    float* hp = reinterpret_cast<float*>(h4);
    for (int i = tid; i < H1D * 4; i += 512) hp[i] = 0.f;

    float c = 0.f;
    const int kind = tid / H1D;          // 0:i 1:f 2:g 3:o (phase-1 role)
    const int r2 = tid / H1D;            // phase-2 row
    const int j2 = tid - r2 * H1D;       // phase-2 hidden unit

    __syncthreads();

#pragma unroll 1
    for (int t = 0; t < T_SEQ; ++t) {
        if (tid < G1D) {
            const float* zp = zx + ((size_t)t * BATCH + b0) * G1D + tid;
            float x0 = zp[0];
            float x1 = zp[G1D];
            float x2 = zp[2 * G1D];
            float x3 = zp[3 * G1D];
            float a0 = 0.f, a1 = 0.f, a2 = 0.f, a3 = 0.f;
#pragma unroll
            for (int j = 0; j < H1D; ++j) {
                float4 hv = h4[j];
                float u = Ureg[j];
                a0 = fmaf(hv.x, u, a0);
                a1 = fmaf(hv.y, u, a1);
                a2 = fmaf(hv.z, u, a2);
                a3 = fmaf(hv.w, u, a3);
            }
            a0 += x0; a1 += x1; a2 += x2; a3 += x3;
            if (kind == 2) {               // g gate: relu
                a0 = fmaxf(a0, 0.f); a1 = fmaxf(a1, 0.f);
                a2 = fmaxf(a2, 0.f); a3 = fmaxf(a3, 0.f);
            } else {                       // i,f,o: sigmoid
                a0 = 1.f / (1.f + __expf(-a0));
                a1 = 1.f / (1.f + __expf(-a1));
                a2 = 1.f / (1.f + __expf(-a2));
                a3 = 1.f / (1.f + __expf(-a3));
            }
            zs[0 * G1D + tid] = a0;
            zs[1 * G1D + tid] = a1;
            zs[2 * G1D + tid] = a2;
            zs[3 * G1D + tid] = a3;
        }
        __syncthreads();
        if (tid < G1D) {
            float gi = zs[r2 * G1D + j2];
            float gf = zs[r2 * G1D + H1D + j2];
            float gg = zs[r2 * G1D + 2 * H1D + j2];
            float go = zs[r2 * G1D + 3 * H1D + j2];
            c = fmaf(gf, c, gi * gg);
            float h = go * fmaxf(c, 0.f);
            hp[j2 * 4 + r2] = h;
            hout[((size_t)t * BATCH + b0 + r2) * H1D + j2] = h;
        }
        __syncthreads();
    }
}

// ---------------- layer-2 scan: U2 (128x512=256KB) split regs(64) + smem(64)
#define UREG2 64
__global__ __launch_bounds__(512, 1)
void lstm_scan2(const float* __restrict__ zx, const float* __restrict__ U,
                float* __restrict__ h2out)
{
    extern __shared__ float sm[];
    float* U2s = sm;                        // [64][512]: rows j=64..127
    float* hp  = sm + UREG2 * G2D;          // h: [H2][4]
    float* zs  = hp + H2D * 4;              // [4][G2]

    const int tid = threadIdx.x;
    const int b0 = blockIdx.x * 4;

    float Ureg[UREG2];
#pragma unroll
    for (int j = 0; j < UREG2; ++j) Ureg[j] = U[j * G2D + tid];
    for (int idx = tid; idx < (H2D - UREG2) * G2D; idx += 512)
        U2s[idx] = U[(size_t)UREG2 * G2D + idx];
    for (int i = tid; i < H2D * 4; i += 512) hp[i] = 0.f;

    float c = 0.f;
    const int kind = tid >> 7;
    const int r2 = tid >> 7;
    const int j2 = tid & 127;

    __syncthreads();

#pragma unroll 1
    for (int t = 0; t < T_SEQ; ++t) {
        {
            const float* zp = zx + ((size_t)t * BATCH + b0) * G2D + tid;
            float x0 = zp[0];
            float x1 = zp[G2D];
            float x2 = zp[2 * G2D];
            float x3 = zp[3 * G2D];
            float a0 = 0.f, a1 = 0.f, a2 = 0.f, a3 = 0.f;
            const float4* h4 = reinterpret_cast<const float4*>(hp);
#pragma unroll
            for (int j = 0; j < UREG2; ++j) {
                float4 hv = h4[j];
                float u = Ureg[j];
                a0 = fmaf(hv.x, u, a0);
                a1 = fmaf(hv.y, u, a1);
                a2 = fmaf(hv.z, u, a2);
                a3 = fmaf(hv.w, u, a3);
            }
#pragma unroll
            for (int j = 0; j < H2D - UREG2; ++j) {
                float4 hv = h4[UREG2 + j];
                float u = U2s[j * G2D + tid];
                a0 = fmaf(hv.x, u, a0);
                a1 = fmaf(hv.y, u, a1);
                a2 = fmaf(hv.z, u, a2);
                a3 = fmaf(hv.w, u, a3);
            }
            a0 += x0; a1 += x1; a2 += x2; a3 += x3;
            if (kind == 2) {
                a0 = fmaxf(a0, 0.f); a1 = fmaxf(a1, 0.f);
                a2 = fmaxf(a2, 0.f); a3 = fmaxf(a3, 0.f);
            } else {
                a0 = 1.f / (1.f + __expf(-a0));
                a1 = 1.f / (1.f + __expf(-a1));
                a2 = 1.f / (1.f + __expf(-a2));
                a3 = 1.f / (1.f + __expf(-a3));
            }
            zs[0 * G2D + tid] = a0;
            zs[1 * G2D + tid] = a1;
            zs[2 * G2D + tid] = a2;
            zs[3 * G2D + tid] = a3;
        }
        __syncthreads();
        {
            float gi = zs[r2 * G2D + j2];
            float gf = zs[r2 * G2D + H2D + j2];
            float gg = zs[r2 * G2D + 2 * H2D + j2];
            float go = zs[r2 * G2D + 3 * H2D + j2];
            c = fmaf(gf, c, gi * gg);
            float h = go * fmaxf(c, 0.f);
            hp[j2 * 4 + r2] = h;
            if (t == T_SEQ - 1) h2out[(b0 + r2) * H2D + j2] = h;
        }
        __syncthreads();
    }
}

// ---------------- dense head + softmax -------------------------------------
__global__ void head_kernel(const float* __restrict__ h2, const float* __restrict__ Wd,
                            const float* __restrict__ bd, float* __restrict__ out)
{
    __shared__ float hsh[H2D];
    const int b = blockIdx.x;
    const int lane = threadIdx.x;
    for (int j = lane; j < H2D; j += 32) hsh[j] = h2[b * H2D + j];
    __syncthreads();

    float acc = 0.f;
    if (lane < NC) {
        acc = bd[lane];
#pragma unroll
        for (int j = 0; j < H2D; ++j) acc = fmaf(hsh[j], Wd[j * NC + lane], acc);
    }
    float v = (lane < NC) ? acc : -FLT_MAX;
#pragma unroll
    for (int off = 16; off > 0; off >>= 1)
        v = fmaxf(v, __shfl_xor_sync(0xffffffffu, v, off));
    float e = (lane < NC) ? expf(acc - v) : 0.f;
    float s = e;
#pragma unroll
    for (int off = 16; off > 0; off >>= 1)
        s += __shfl_xor_sync(0xffffffffu, s, off);
    if (lane < NC) out[b * NC + lane] = e / s;
}

// ---------------- launch ----------------------------------------------------
extern "C" void kernel_launch(void* const* d_in, const int* in_sizes, int n_in,
                              void* d_out, int out_size)
{
    const float* x  = (const float*)d_in[0];
    const float* W1 = (const float*)d_in[1];
    const float* U1 = (const float*)d_in[2];
    const float* b1 = (const float*)d_in[3];
    const float* W2 = (const float*)d_in[4];
    const float* U2 = (const float*)d_in[5];
    const float* b2 = (const float*)d_in[6];
    const float* Wd = (const float*)d_in[7];
    const float* bd = (const float*)d_in[8];
    float* out = (float*)d_out;

    const int gemm_smem  = (KMAX * AP + KMAX * BN) * 4;                 // 67584 B
    const int scan2_smem = (UREG2 * G2D + H2D * 4 + 4 * G2D) * 4;       // 141312 B
    cudaFuncSetAttribute(gemm_ff,   cudaFuncAttributeMaxDynamicSharedMemorySize, gemm_smem);
    cudaFuncSetAttribute(lstm_scan2, cudaFuncAttributeMaxDynamicSharedMemorySize, scan2_smem);

    float *zx1p, *h1p, *zx2p, *h2p;
    cudaGetSymbolAddress((void**)&zx1p, g_zx1);
    cudaGetSymbolAddress((void**)&h1p,  g_h1);
    cudaGetSymbolAddress((void**)&zx2p, g_zx2);
    cudaGetSymbolAddress((void**)&h2p,  g_h2);

    const int M = T_SEQ * BATCH;

    // zx1 = x @ W1 + b1   (A gathered from x[b][t][:])
    gemm_ff<<<dim3(M / BM, (G1D + BN - 1) / BN), 256, gemm_smem>>>(
        x, W1, b1, zx1p, M, G1D, IND, 1);

    // layer-1 recurrent scan
    lstm_scan1<<<BATCH / 4, 512>>>(zx1p, U1, h1p);

    // zx2 = h1_seq @ W2 + b2
    gemm_ff<<<dim3(M / BM, G2D / BN), 256, gemm_smem>>>(
        h1p, W2, b2, zx2p, M, G2D, H1D, 0);

    // layer-2 recurrent scan (keeps only final h)
    lstm_scan2<<<BATCH / 4, 512, scan2_smem>>>(zx2p, U2, h2p);

    // dense + softmax
    head_kernel<<<BATCH, 32>>>(h2p, Wd, bd, out);
}

// round 2
// speedup vs baseline: 1.0376x; 1.0376x over previous
#include <cuda_runtime.h>
#include <math.h>
#include <float.h>

// Problem dims
#define T_SEQ 256
#define BATCH 512
#define IND   128
#define H1D   100
#define G1D   400     // 4*H1
#define H2D   128
#define G2D   512     // 4*H2
#define NC    19

typedef unsigned long long u64;

// packed f32x2 helpers (SASS FFMA2 — only reachable via PTX)
__device__ __forceinline__ void ffma2(u64 &d, u64 a, u64 b) {
    asm("fma.rn.f32x2 %0, %1, %2, %0;" : "+l"(d) : "l"(a), "l"(b));
}
__device__ __forceinline__ u64 pack2(float x, float y) {
    u64 r; asm("mov.b64 %0, {%1, %2};" : "=l"(r) : "f"(x), "f"(y)); return r;
}
__device__ __forceinline__ float2 unpk(u64 v) {
    float2 r; asm("mov.b64 {%0, %1}, %2;" : "=f"(r.x), "=f"(r.y) : "l"(v)); return r;
}

// ---------------- scratch (device globals: no allocation allowed) ----------
__device__ float g_zx1[256u*512u*400u];   // [T][B][4*H1]
__device__ float g_h1 [256u*512u*100u];   // [T][B][H1]
__device__ float g_zx2[256u*512u*512u];   // [T][B][4*H2]
__device__ float g_h2 [512u*128u];        // [B][H2]

// ---------------- generic feedforward GEMM: C = A(MxK) * B(KxN) + bias -----
#define BM 64
#define BN 64
#define KMAX 128
#define AP 68

__global__ __launch_bounds__(256, 3)
void gemm_ff(const float* __restrict__ A, const float* __restrict__ Bw,
             const float* __restrict__ bias, float* __restrict__ C,
             int M, int N, int K, int mode)
{
    extern __shared__ float sm[];
    float* As = sm;                 // [KMAX][AP] transposed A tile
    float* Bs = sm + KMAX * AP;     // [KMAX][BN]

    const int tid = threadIdx.x;
    const int m0 = blockIdx.x * BM;
    const int n0 = blockIdx.y * BN;

    for (int idx = tid; idx < BM * K; idx += 256) {
        int mloc = idx / K;
        int k = idx - mloc * K;
        int m = m0 + mloc;
        size_t arow;
        if (mode) { int t = m >> 9; int b = m & 511; arow = ((size_t)(b * T_SEQ + t)) * IND; }
        else      { arow = (size_t)m * K; }
        As[k * AP + mloc] = A[arow + k];
    }
    for (int idx = tid; idx < K * BN; idx += 256) {
        int k = idx >> 6;
        int n = idx & 63;
        int gn = n0 + n;
        Bs[k * BN + n] = (gn < N) ? Bw[(size_t)k * N + gn] : 0.f;
    }
    __syncthreads();

    const int tx = tid & 15, ty = tid >> 4;
    // acc2[ip][j]: f32x2 lanes = row pair (ty*4 + 2*ip, +1), column n0+tx*4+j
    u64 acc2[2][4];
#pragma unroll
    for (int i = 0; i < 2; i++)
#pragma unroll
        for (int j = 0; j < 4; j++) acc2[i][j] = 0ull;

#pragma unroll 4
    for (int k = 0; k < K; ++k) {
        ulonglong2 av = *reinterpret_cast<const ulonglong2*>(&As[k * AP + ty * 4]);
        float4 bv = *reinterpret_cast<const float4*>(&Bs[k * BN + tx * 4]);
        u64 b0 = pack2(bv.x, bv.x);
        u64 b1 = pack2(bv.y, bv.y);
        u64 b2 = pack2(bv.z, bv.z);
        u64 b3 = pack2(bv.w, bv.w);
        ffma2(acc2[0][0], av.x, b0); ffma2(acc2[0][1], av.x, b1);
        ffma2(acc2[0][2], av.x, b2); ffma2(acc2[0][3], av.x, b3);
        ffma2(acc2[1][0], av.y, b0); ffma2(acc2[1][1], av.y, b1);
        ffma2(acc2[1][2], av.y, b2); ffma2(acc2[1][3], av.y, b3);
    }

    float accf[4][4];
#pragma unroll
    for (int j = 0; j < 4; j++) {
        float2 p = unpk(acc2[0][j]);
        float2 q = unpk(acc2[1][j]);
        accf[0][j] = p.x; accf[1][j] = p.y;
        accf[2][j] = q.x; accf[3][j] = q.y;
    }

#pragma unroll
    for (int i = 0; i < 4; i++) {
        int m = m0 + ty * 4 + i;
        int n = n0 + tx * 4;
        float* cp = &C[(size_t)m * N + n];
        if (n + 3 < N) {
            float4 v;
            v.x = accf[i][0] + bias[n + 0];
            v.y = accf[i][1] + bias[n + 1];
            v.z = accf[i][2] + bias[n + 2];
            v.w = accf[i][3] + bias[n + 3];
            *reinterpret_cast<float4*>(cp) = v;
        } else {
#pragma unroll
            for (int j = 0; j < 4; j++)
                if (n + j < N) cp[j] = accf[i][j] + bias[n + j];
        }
    }
}

// ---------------- layer-1 scan -------------------------------------------
// h stored TRANSPOSED: hT[r][j] (r = batch row within block). One LDS.128
// yields (h_j,h_j+1),(h_j+2,h_j+3) packed pairs. U pairs (U[j],U[j+1]) packed
// in registers (80 j) or transposed smem (20 j). Even/odd-j partials live in
// the two f32x2 lanes; one lane-add at the end.
#define U1REGJ 80
#define U1SMJ  20
__global__ __launch_bounds__(512, 1)
void lstm_scan1(const float* __restrict__ zx, const float* __restrict__ U,
                float* __restrict__ hout)
{
    __shared__ __align__(16) float hT[4 * H1D];          // [r][j]
    __shared__ float zs[4 * G1D];
    __shared__ __align__(16) float U1sT[G1D * U1SMJ];    // [col][jj]

    const int tid = threadIdx.x;
    const int b0 = blockIdx.x * 4;

    u64 Up[U1REGJ / 2];
    if (tid < G1D) {
#pragma unroll
        for (int p = 0; p < U1REGJ / 2; ++p)
            Up[p] = pack2(U[(2 * p) * G1D + tid], U[(2 * p + 1) * G1D + tid]);
#pragma unroll
        for (int jj = 0; jj < U1SMJ; ++jj)
            U1sT[tid * U1SMJ + jj] = U[(U1REGJ + jj) * G1D + tid];
    }
    for (int i = tid; i < 4 * H1D; i += 512) hT[i] = 0.f;

    float c = 0.f;
    const int kind = tid / H1D;
    const int r2 = tid / H1D;
    const int j2 = tid - r2 * H1D;

    __syncthreads();

#pragma unroll 1
    for (int t = 0; t < T_SEQ; ++t) {
        if (tid < G1D) {
            const float* zp = zx + ((size_t)t * BATCH + b0) * G1D + tid;
            float x0 = zp[0];
            float x1 = zp[G1D];
            float x2 = zp[2 * G1D];
            float x3 = zp[3 * G1D];
            u64 ac0 = 0ull, ac1 = 0ull, ac2 = 0ull, ac3 = 0ull;
#pragma unroll
            for (int p4 = 0; p4 < U1REGJ / 4; ++p4) {
                int j0 = 4 * p4;
                ulonglong2 h0 = *reinterpret_cast<const ulonglong2*>(&hT[0 * H1D + j0]);
                ulonglong2 h1 = *reinterpret_cast<const ulonglong2*>(&hT[1 * H1D + j0]);
                ulonglong2 h2 = *reinterpret_cast<const ulonglong2*>(&hT[2 * H1D + j0]);
                ulonglong2 h3 = *reinterpret_cast<const ulonglong2*>(&hT[3 * H1D + j0]);
                u64 ua = Up[2 * p4], ub = Up[2 * p4 + 1];
                ffma2(ac0, h0.x, ua); ffma2(ac0, h0.y, ub);
                ffma2(ac1, h1.x, ua); ffma2(ac1, h1.y, ub);
                ffma2(ac2, h2.x, ua); ffma2(ac2, h2.y, ub);
                ffma2(ac3, h3.x, ua); ffma2(ac3, h3.y, ub);
            }
#pragma unroll
            for (int q = 0; q < U1SMJ / 4; ++q) {
                int j0 = U1REGJ + 4 * q;
                ulonglong2 uu = *reinterpret_cast<const ulonglong2*>(&U1sT[tid * U1SMJ + 4 * q]);
                ulonglong2 h0 = *reinterpret_cast<const ulonglong2*>(&hT[0 * H1D + j0]);
                ulonglong2 h1 = *reinterpret_cast<const ulonglong2*>(&hT[1 * H1D + j0]);
                ulonglong2 h2 = *reinterpret_cast<const ulonglong2*>(&hT[2 * H1D + j0]);
                ulonglong2 h3 = *reinterpret_cast<const ulonglong2*>(&hT[3 * H1D + j0]);
                ffma2(ac0, h0.x, uu.x); ffma2(ac0, h0.y, uu.y);
                ffma2(ac1, h1.x, uu.x); ffma2(ac1, h1.y, uu.y);
                ffma2(ac2, h2.x, uu.x); ffma2(ac2, h2.y, uu.y);
                ffma2(ac3, h3.x, uu.x); ffma2(ac3, h3.y, uu.y);
            }
            float2 s0 = unpk(ac0), s1 = unpk(ac1), s2 = unpk(ac2), s3 = unpk(ac3);
            float a0 = s0.x + s0.y + x0;
            float a1 = s1.x + s1.y + x1;
            float a2 = s2.x + s2.y + x2;
            float a3 = s3.x + s3.y + x3;
            if (kind == 2) {
                a0 = fmaxf(a0, 0.f); a1 = fmaxf(a1, 0.f);
                a2 = fmaxf(a2, 0.f); a3 = fmaxf(a3, 0.f);
            } else {
                a0 = 1.f / (1.f + __expf(-a0));
                a1 = 1.f / (1.f + __expf(-a1));
                a2 = 1.f / (1.f + __expf(-a2));
                a3 = 1.f / (1.f + __expf(-a3));
            }
            zs[0 * G1D + tid] = a0;
            zs[1 * G1D + tid] = a1;
            zs[2 * G1D + tid] = a2;
            zs[3 * G1D + tid] = a3;
        }
        __syncthreads();
        if (tid < G1D) {
            float gi = zs[r2 * G1D + j2];
            float gf = zs[r2 * G1D + H1D + j2];
            float gg = zs[r2 * G1D + 2 * H1D + j2];
            float go = zs[r2 * G1D + 3 * H1D + j2];
            c = fmaf(gf, c, gi * gg);
            float h = go * fmaxf(c, 0.f);
            hT[r2 * H1D + j2] = h;
            hout[((size_t)t * BATCH + b0 + r2) * H1D + j2] = h;
        }
        __syncthreads();
    }
}

// ---------------- layer-2 scan -------------------------------------------
#define U2REGJ 64
#define U2SMJ  64
#define U2P    68   // padded row stride for transposed smem U (conflict-free LDS.128)
__global__ __launch_bounds__(512, 1)
void lstm_scan2(const float* __restrict__ zx, const float* __restrict__ U,
                float* __restrict__ h2out)
{
    extern __shared__ float sm2[];
    float* U2sT = sm2;                       // [G2D][U2P]
    float* hT   = sm2 + G2D * U2P;           // [4][H2D]
    float* zs   = hT + 4 * H2D;              // [4][G2D]

    const int tid = threadIdx.x;
    const int b0 = blockIdx.x * 4;

    u64 Up[U2REGJ / 2];
#pragma unroll
    for (int p = 0; p < U2REGJ / 2; ++p)
        Up[p] = pack2(U[(2 * p) * G2D + tid], U[(2 * p + 1) * G2D + tid]);
#pragma unroll
    for (int jj = 0; jj < U2SMJ; ++jj)
        U2sT[tid * U2P + jj] = U[(size_t)(U2REGJ + jj) * G2D + tid];
    for (int i = tid; i < 4 * H2D; i += 512) hT[i] = 0.f;

    float c = 0.f;
    const int kind = tid >> 7;
    const int r2 = tid >> 7;
    const int j2 = tid & 127;

    __syncthreads();

#pragma unroll 1
    for (int t = 0; t < T_SEQ; ++t) {
        {
            const float* zp = zx + ((size_t)t * BATCH + b0) * G2D + tid;
            float x0 = zp[0];
            float x1 = zp[G2D];
            float x2 = zp[2 * G2D];
            float x3 = zp[3 * G2D];
            u64 ac0 = 0ull, ac1 = 0ull, ac2 = 0ull, ac3 = 0ull;
#pragma unroll
            for (int p4 = 0; p4 < U2REGJ / 4; ++p4) {
                int j0 = 4 * p4;
                ulonglong2 h0 = *reinterpret_cast<const ulonglong2*>(&hT[0 * H2D + j0]);
                ulonglong2 h1 = *reinterpret_cast<const ulonglong2*>(&hT[1 * H2D + j0]);
                ulonglong2 h2 = *reinterpret_cast<const ulonglong2*>(&hT[2 * H2D + j0]);
                ulonglong2 h3 = *reinterpret_cast<const ulonglong2*>(&hT[3 * H2D + j0]);
                u64 ua = Up[2 * p4], ub = Up[2 * p4 + 1];
                ffma2(ac0, h0.x, ua); ffma2(ac0, h0.y, ub);
                ffma2(ac1, h1.x, ua); ffma2(ac1, h1.y, ub);
                ffma2(ac2, h2.x, ua); ffma2(ac2, h2.y, ub);
                ffma2(ac3, h3.x, ua); ffma2(ac3, h3.y, ub);
            }
#pragma unroll
            for (int q = 0; q < U2SMJ / 4; ++q) {
                int j0 = U2REGJ + 4 * q;
                ulonglong2 uu = *reinterpret_cast<const ulonglong2*>(&U2sT[tid * U2P + 4 * q]);
                ulonglong2 h0 = *reinterpret_cast<const ulonglong2*>(&hT[0 * H2D + j0]);
                ulonglong2 h1 = *reinterpret_cast<const ulonglong2*>(&hT[1 * H2D + j0]);
                ulonglong2 h2 = *reinterpret_cast<const ulonglong2*>(&hT[2 * H2D + j0]);
                ulonglong2 h3 = *reinterpret_cast<const ulonglong2*>(&hT[3 * H2D + j0]);
                ffma2(ac0, h0.x, uu.x); ffma2(ac0, h0.y, uu.y);
                ffma2(ac1, h1.x, uu.x); ffma2(ac1, h1.y, uu.y);
                ffma2(ac2, h2.x, uu.x); ffma2(ac2, h2.y, uu.y);
                ffma2(ac3, h3.x, uu.x); ffma2(ac3, h3.y, uu.y);
            }
            float2 s0 = unpk(ac0), s1 = unpk(ac1), s2 = unpk(ac2), s3 = unpk(ac3);
            float a0 = s0.x + s0.y + x0;
            float a1 = s1.x + s1.y + x1;
            float a2 = s2.x + s2.y + x2;
            float a3 = s3.x + s3.y + x3;
            if (kind == 2) {
                a0 = fmaxf(a0, 0.f); a1 = fmaxf(a1, 0.f);
                a2 = fmaxf(a2, 0.f); a3 = fmaxf(a3, 0.f);
            } else {
                a0 = 1.f / (1.f + __expf(-a0));
                a1 = 1.f / (1.f + __expf(-a1));
                a2 = 1.f / (1.f + __expf(-a2));
                a3 = 1.f / (1.f + __expf(-a3));
            }
            zs[0 * G2D + tid] = a0;
            zs[1 * G2D + tid] = a1;
            zs[2 * G2D + tid] = a2;
            zs[3 * G2D + tid] = a3;
        }
        __syncthreads();
        {
            float gi = zs[r2 * G2D + j2];
            float gf = zs[r2 * G2D + H2D + j2];
            float gg = zs[r2 * G2D + 2 * H2D + j2];
            float go = zs[r2 * G2D + 3 * H2D + j2];
            c = fmaf(gf, c, gi * gg);
            float h = go * fmaxf(c, 0.f);
            hT[r2 * H2D + j2] = h;
            if (t == T_SEQ - 1) h2out[(b0 + r2) * H2D + j2] = h;
        }
        __syncthreads();
    }
}

// ---------------- dense head + softmax -------------------------------------
__global__ void head_kernel(const float* __restrict__ h2, const float* __restrict__ Wd,
                            const float* __restrict__ bd, float* __restrict__ out)
{
    __shared__ float hsh[H2D];
    const int b = blockIdx.x;
    const int lane = threadIdx.x;
    for (int j = lane; j < H2D; j += 32) hsh[j] = h2[b * H2D + j];
    __syncthreads();

    float acc = 0.f;
    if (lane < NC) {
        acc = bd[lane];
#pragma unroll
        for (int j = 0; j < H2D; ++j) acc = fmaf(hsh[j], Wd[j * NC + lane], acc);
    }
    float v = (lane < NC) ? acc : -FLT_MAX;
#pragma unroll
    for (int off = 16; off > 0; off >>= 1)
        v = fmaxf(v, __shfl_xor_sync(0xffffffffu, v, off));
    float e = (lane < NC) ? expf(acc - v) : 0.f;
    float s = e;
#pragma unroll
    for (int off = 16; off > 0; off >>= 1)
        s += __shfl_xor_sync(0xffffffffu, s, off);
    if (lane < NC) out[b * NC + lane] = e / s;
}

// ---------------- launch ----------------------------------------------------
extern "C" void kernel_launch(void* const* d_in, const int* in_sizes, int n_in,
                              void* d_out, int out_size)
{
    const float* x  = (const float*)d_in[0];
    const float* W1 = (const float*)d_in[1];
    const float* U1 = (const float*)d_in[2];
    const float* b1 = (const float*)d_in[3];
    const float* W2 = (const float*)d_in[4];
    const float* U2 = (const float*)d_in[5];
    const float* b2 = (const float*)d_in[6];
    const float* Wd = (const float*)d_in[7];
    const float* bd = (const float*)d_in[8];
    float* out = (float*)d_out;

    const int gemm_smem  = (KMAX * AP + KMAX * BN) * 4;
    const int scan2_smem = (G2D * U2P + 4 * H2D + 4 * G2D) * 4;   // 149504 B
    cudaFuncSetAttribute(gemm_ff,    cudaFuncAttributeMaxDynamicSharedMemorySize, gemm_smem);
    cudaFuncSetAttribute(lstm_scan2, cudaFuncAttributeMaxDynamicSharedMemorySize, scan2_smem);

    float *zx1p, *h1p, *zx2p, *h2p;
    cudaGetSymbolAddress((void**)&zx1p, g_zx1);
    cudaGetSymbolAddress((void**)&h1p,  g_h1);
    cudaGetSymbolAddress((void**)&zx2p, g_zx2);
    cudaGetSymbolAddress((void**)&h2p,  g_h2);

    const int M = T_SEQ * BATCH;

    gemm_ff<<<dim3(M / BM, (G1D + BN - 1) / BN), 256, gemm_smem>>>(
        x, W1, b1, zx1p, M, G1D, IND, 1);

    lstm_scan1<<<BATCH / 4, 512>>>(zx1p, U1, h1p);

    gemm_ff<<<dim3(M / BM, G2D / BN), 256, gemm_smem>>>(
        h1p, W2, b2, zx2p, M, G2D, H1D, 0);

    lstm_scan2<<<BATCH / 4, 512, scan2_smem>>>(zx2p, U2, h2p);

    head_kernel<<<BATCH, 32>>>(h2p, Wd, bd, out);
}